// round 1
// baseline (speedup 1.0000x reference)
#include <cuda_runtime.h>
#include <cuda_bf16.h>

#define Bv 4
#define Tv 512
#define Iv 512
#define Hv 8
#define Dv 512
#define Vv 32000

// scratch (allocation-free rule: __device__ globals)
__device__ int   g_leader[Bv * Iv];
__device__ float g_encW[Bv * Iv];
__device__ int   g_nu[Bv];

// ---------------------------------------------------------------------------
// Kernel A: per-batch duplicate-token resolution. leader[i] = min j with
// tok[j]==tok[i]; n_unique = #(leader==i). Runs once per batch (4 blocks).
// ---------------------------------------------------------------------------
__global__ __launch_bounds__(Iv) void dedup_kernel(const int* __restrict__ tok) {
    int b = blockIdx.x, i = threadIdx.x;
    __shared__ int st[Iv];
    __shared__ int cnt;
    if (i == 0) cnt = 0;
    st[i] = tok[b * Iv + i];
    __syncthreads();
    int me = st[i];
    int lead = i;
    for (int j = 0; j < i; j++) {
        if (st[j] == me) { lead = j; break; }
    }
    g_leader[b * Iv + i] = lead;
    if (lead == i) atomicAdd(&cnt, 1);
    __syncthreads();
    if (i == 0) g_nu[b] = cnt;
}

// ---------------------------------------------------------------------------
// Kernel B: encW[b,i] = dot(enc_output[b,i,:], W_pgen[0:D]). One warp per row.
// ---------------------------------------------------------------------------
__global__ void encw_kernel(const float* __restrict__ enc,
                            const float* __restrict__ W) {
    int warp = (blockIdx.x * blockDim.x + threadIdx.x) >> 5;
    int lane = threadIdx.x & 31;
    if (warp >= Bv * Iv) return;
    const float* row = enc + (long)warp * Dv;
    float acc = 0.f;
    #pragma unroll
    for (int d = lane; d < Dv; d += 32) acc = fmaf(row[d], W[d], acc);
    #pragma unroll
    for (int o = 16; o; o >>= 1) acc += __shfl_down_sync(0xffffffffu, acc, o);
    if (lane == 0) g_encW[warp] = acc;
}

// ---------------------------------------------------------------------------
// Block reduction (512 threads)
// ---------------------------------------------------------------------------
__device__ __forceinline__ float block_reduce_sum(float v, float* sred) {
    int lane = threadIdx.x & 31;
    int w = threadIdx.x >> 5;
    #pragma unroll
    for (int o = 16; o; o >>= 1) v += __shfl_down_sync(0xffffffffu, v, o);
    if (lane == 0) sred[w] = v;
    __syncthreads();
    if (w == 0) {
        float x = (lane < 16) ? sred[lane] : 0.f;
        #pragma unroll
        for (int o = 8; o; o >>= 1) x += __shfl_down_sync(0xffffffffu, x, o);
        if (lane == 0) sred[0] = x;
    }
    __syncthreads();
    float r = sred[0];
    __syncthreads();
    return r;
}

// ---------------------------------------------------------------------------
// Kernel C (heavy): one block per (b,t) row.
//  1. w[i] = mean_h attn_heads[b,h,t,i]
//  2. p_gen = sigmoid( sum_i w[i]*encW[b,i] + dec.W2 + tar.W3 + b )
//  3. smem scatter via leader index; exp-sum; base = 1/denom
//  4. stream V with float4: final = pg*gen + (1-pg)*base; pointer = base
//  5. fixup the <=512 touched vocab slots
// ---------------------------------------------------------------------------
__global__ __launch_bounds__(512) void pointer_fuse_kernel(
    const int* __restrict__ tok,
    const float* __restrict__ tar,
    const float* __restrict__ gen,
    const float* __restrict__ dec,
    const float* __restrict__ attn_heads,
    const float* __restrict__ W,
    const float* __restrict__ bpg,
    float* __restrict__ out)
{
    const int row = blockIdx.x;        // b*T + t
    const int b   = row >> 9;          // T = 512
    const int t   = row & 511;
    const int tid = threadIdx.x;       // 512 threads == I == D

    __shared__ float ss[Iv];           // scatter sums (indexed by leader)
    __shared__ int   stok[Iv];
    __shared__ int   slead[Iv];
    __shared__ float sred[32];

    stok[tid]  = tok[b * Iv + tid];
    slead[tid] = g_leader[b * Iv + tid];
    ss[tid] = 0.f;

    // head-mean attention weight for column i = tid
    float w = 0.f;
    long base_a = ((long)b * Hv) * ((long)Tv * Iv) + (long)t * Iv + tid;
    #pragma unroll
    for (int h = 0; h < Hv; h++) w += attn_heads[base_a + (long)h * Tv * Iv];
    w *= 0.125f;

    // p_gen partial: context-collapsed term + dec/tar dots
    float acc = w * g_encW[b * Iv + tid];
    acc = fmaf(dec[(long)row * Dv + tid], W[Dv + tid], acc);
    acc = fmaf(tar[(long)row * Dv + tid], W[2 * Dv + tid], acc);

    __syncthreads();                   // ss zeroed
    atomicAdd(&ss[slead[tid]], w);     // scatter (few conflicts)

    float pgsum = block_reduce_sum(acc, sred);  // syncs make atomics visible

    const bool active = (slead[tid] == tid);
    float e = active ? expf(ss[tid]) : 0.f;
    float esum = block_reduce_sum(e, sred);

    const int   nu    = g_nu[b];
    const float denom = esum + (float)(Vv - nu);
    const float base  = 1.f / denom;
    const float pg    = 1.f / (1.f + expf(-(pgsum + bpg[0])));
    const float omp   = 1.f - pg;
    const float pb    = omp * base;

    // stream the vocab dimension
    const float4* g4 = (const float4*)(gen + (long)row * Vv);
    float4* f4 = (float4*)(out + (long)row * Vv);
    float4* p4 = (float4*)(out + (long)(Bv * Tv) * Vv + (long)row * Vv);
    const float4 pconst = make_float4(base, base, base, base);

    #pragma unroll 4
    for (int v = tid; v < Vv / 4; v += 512) {
        float4 g = g4[v];
        float4 f;
        f.x = fmaf(pg, g.x, pb);
        f.y = fmaf(pg, g.y, pb);
        f.z = fmaf(pg, g.z, pb);
        f.w = fmaf(pg, g.w, pb);
        f4[v] = f;
        p4[v] = pconst;
    }
    __syncthreads();

    // fixup touched slots
    if (active) {
        int v = stok[tid];
        float eb = e * base;
        out[(long)(Bv * Tv) * Vv + (long)row * Vv + v] = eb;
        out[(long)row * Vv + v] = fmaf(pg, gen[(long)row * Vv + v], omp * eb);
    }
    if (tid == 0) {
        out[2L * Bv * Tv * Vv + row] = pg;   // p_gen (B,T)
    }
}

// ---------------------------------------------------------------------------
// Launch. Input order (metadata): inp_tokens, tar_embedded, generator_output,
// enc_output, dec_state, attn_heads, W_pgen, b_pgen.
// Output: final (B,T,V) ++ pointer (B,T,V) ++ p_gen (B,T), float32.
// ---------------------------------------------------------------------------
extern "C" void kernel_launch(void* const* d_in, const int* in_sizes, int n_in,
                              void* d_out, int out_size) {
    const int*   tok  = (const int*)  d_in[0];
    const float* tar  = (const float*)d_in[1];
    const float* gen  = (const float*)d_in[2];
    const float* enc  = (const float*)d_in[3];
    const float* dec  = (const float*)d_in[4];
    const float* ah   = (const float*)d_in[5];
    const float* W    = (const float*)d_in[6];
    const float* bpg  = (const float*)d_in[7];
    float* out = (float*)d_out;

    dedup_kernel<<<Bv, Iv>>>(tok);
    encw_kernel<<<(Bv * Iv * 32 + 255) / 256, 256>>>(enc, W);
    pointer_fuse_kernel<<<Bv * Tv, 512>>>(tok, tar, gen, dec, ah, W, bpg, out);
}

// round 2
// speedup vs baseline: 1.0234x; 1.0234x over previous
#include <cuda_runtime.h>
#include <cuda_bf16.h>

#define Bv 4
#define Tv 512
#define Iv 512
#define Hv 8
#define Dv 512
#define Vv 32000

// scratch (allocation-free rule: __device__ globals)
__device__ int   g_leader[Bv * Iv];
__device__ float g_encW[Bv * Iv];
__device__ int   g_nu[Bv];

// ---------------------------------------------------------------------------
// Prep kernel: blocks [0,128) compute encW (16 warps each, one warp per
// (b,i) row); blocks [128,132) do per-batch branchless dedup.
//   encW[b,i] = dot(enc_output[b,i,:], W_pgen[0:D])
//   leader[i] = min j with tok[j]==tok[i];  nu = #unique
// ---------------------------------------------------------------------------
__global__ __launch_bounds__(512) void prep_kernel(const int* __restrict__ tok,
                                                   const float* __restrict__ enc,
                                                   const float* __restrict__ W) {
    __shared__ int st[Iv];
    if (blockIdx.x < 128) {
        int warp = blockIdx.x * 16 + (threadIdx.x >> 5);   // 0..2047 = b*I+i
        int lane = threadIdx.x & 31;
        const float* row = enc + (long)warp * Dv;
        float acc = 0.f;
        #pragma unroll
        for (int d = lane; d < Dv; d += 32) acc = fmaf(row[d], W[d], acc);
        #pragma unroll
        for (int o = 16; o; o >>= 1) acc += __shfl_down_sync(0xffffffffu, acc, o);
        if (lane == 0) g_encW[warp] = acc;
    } else {
        int b = blockIdx.x - 128;
        int i = threadIdx.x;
        st[i] = tok[b * Iv + i];
        __syncthreads();
        int me = st[i];
        int lead = i;           // first (min-index) match; branchless, ILP-friendly
        #pragma unroll 8
        for (int j = 0; j < Iv; j++) {
            bool m = (st[j] == me) && (j < lead);
            lead = m ? j : lead;
        }
        g_leader[b * Iv + i] = lead;
        int n = __syncthreads_count(lead == i);
        if (i == 0) g_nu[b] = n;
    }
}

// ---------------------------------------------------------------------------
// Block reduction (512 threads)
// ---------------------------------------------------------------------------
__device__ __forceinline__ float block_reduce_sum(float v, float* sred) {
    int lane = threadIdx.x & 31;
    int w = threadIdx.x >> 5;
    #pragma unroll
    for (int o = 16; o; o >>= 1) v += __shfl_down_sync(0xffffffffu, v, o);
    if (lane == 0) sred[w] = v;
    __syncthreads();
    if (w == 0) {
        float x = (lane < 16) ? sred[lane] : 0.f;
        #pragma unroll
        for (int o = 8; o; o >>= 1) x += __shfl_down_sync(0xffffffffu, x, o);
        if (lane == 0) sred[0] = x;
    }
    __syncthreads();
    float r = sred[0];
    __syncthreads();
    return r;
}

// ---------------------------------------------------------------------------
// Fused heavy kernel: one block per (b,t) row.
//  1. w[i] = mean_h attn_heads[b,h,t,i]
//  2. p_gen = sigmoid( sum_i w[i]*encW[b,i] + dec.W2 + tar.W3 + b )
//  3. smem scatter via leader; exp-sum; base = 1/denom
//  4. hoisted scattered gen loads (overlap with stream)
//  5. stream V with float4 + streaming cache hints
//  6. fixup the <=512 touched vocab slots (stores only)
// ---------------------------------------------------------------------------
__global__ __launch_bounds__(512) void pointer_fuse_kernel(
    const int* __restrict__ tok,
    const float* __restrict__ tar,
    const float* __restrict__ gen,
    const float* __restrict__ dec,
    const float* __restrict__ attn_heads,
    const float* __restrict__ W,
    const float* __restrict__ bpg,
    float* __restrict__ out)
{
    const int row = blockIdx.x;        // b*T + t
    const int b   = row >> 9;          // T = 512
    const int t   = row & 511;
    const int tid = threadIdx.x;       // 512 threads == I == D

    __shared__ float ss[Iv];           // scatter sums (indexed by leader)
    __shared__ int   stok[Iv];
    __shared__ int   slead[Iv];
    __shared__ float sred[32];

    stok[tid]  = tok[b * Iv + tid];
    slead[tid] = g_leader[b * Iv + tid];
    ss[tid] = 0.f;

    // head-mean attention weight for column i = tid
    float w = 0.f;
    long base_a = ((long)b * Hv) * ((long)Tv * Iv) + (long)t * Iv + tid;
    #pragma unroll
    for (int h = 0; h < Hv; h++) w += attn_heads[base_a + (long)h * Tv * Iv];
    w *= 0.125f;

    // p_gen partial: context-collapsed term + dec/tar dots
    float acc = w * g_encW[b * Iv + tid];
    acc = fmaf(dec[(long)row * Dv + tid], W[Dv + tid], acc);
    acc = fmaf(tar[(long)row * Dv + tid], W[2 * Dv + tid], acc);

    __syncthreads();                   // ss zeroed
    atomicAdd(&ss[slead[tid]], w);     // scatter (few conflicts)

    float pgsum = block_reduce_sum(acc, sred);  // syncs make atomics visible

    const bool active = (slead[tid] == tid);
    float e = active ? expf(ss[tid]) : 0.f;
    float esum = block_reduce_sum(e, sred);

    const int   nu    = g_nu[b];
    const float denom = esum + (float)(Vv - nu);
    const float base  = 1.f / denom;
    const float pg    = 1.f / (1.f + expf(-(pgsum + bpg[0])));
    const float omp   = 1.f - pg;
    const float pb    = omp * base;

    // hoist the scattered gen loads for the fixup: overlap with streaming
    const int myv = stok[tid];
    float gscat = 0.f;
    if (active) gscat = __ldg(&gen[(long)row * Vv + myv]);

    // stream the vocab dimension (pure bandwidth; evict-first hints)
    const float4* g4 = (const float4*)(gen + (long)row * Vv);
    float4* f4 = (float4*)(out + (long)row * Vv);
    float4* p4 = (float4*)(out + (long)(Bv * Tv) * Vv + (long)row * Vv);
    const float4 pconst = make_float4(base, base, base, base);

    #pragma unroll 4
    for (int v = tid; v < Vv / 4; v += 512) {
        float4 g = __ldcs(&g4[v]);
        float4 f;
        f.x = fmaf(pg, g.x, pb);
        f.y = fmaf(pg, g.y, pb);
        f.z = fmaf(pg, g.z, pb);
        f.w = fmaf(pg, g.w, pb);
        __stcs(&f4[v], f);
        __stcs(&p4[v], pconst);
    }
    __syncthreads();

    // fixup touched slots (stores only — loads were hoisted)
    if (active) {
        float eb = e * base;
        out[(long)(Bv * Tv) * Vv + (long)row * Vv + myv] = eb;
        out[(long)row * Vv + myv] = fmaf(pg, gscat, omp * eb);
    }
    if (tid == 0) {
        out[2L * Bv * Tv * Vv + row] = pg;   // p_gen (B,T)
    }
}

// ---------------------------------------------------------------------------
// Launch. Input order (metadata): inp_tokens, tar_embedded, generator_output,
// enc_output, dec_state, attn_heads, W_pgen, b_pgen.
// Output: final (B,T,V) ++ pointer (B,T,V) ++ p_gen (B,T), float32.
// ---------------------------------------------------------------------------
extern "C" void kernel_launch(void* const* d_in, const int* in_sizes, int n_in,
                              void* d_out, int out_size) {
    const int*   tok  = (const int*)  d_in[0];
    const float* tar  = (const float*)d_in[1];
    const float* gen  = (const float*)d_in[2];
    const float* enc  = (const float*)d_in[3];
    const float* dec  = (const float*)d_in[4];
    const float* ah   = (const float*)d_in[5];
    const float* W    = (const float*)d_in[6];
    const float* bpg  = (const float*)d_in[7];
    float* out = (float*)d_out;

    prep_kernel<<<132, 512>>>(tok, enc, W);
    pointer_fuse_kernel<<<Bv * Tv, 512>>>(tok, tar, gen, dec, ah, W, bpg, out);
}

// round 3
// speedup vs baseline: 1.0768x; 1.0522x over previous
#include <cuda_runtime.h>
#include <cuda_bf16.h>

#define Bv 4
#define Tv 512
#define Iv 512
#define Hv 8
#define Dv 512
#define Vv 32000
#define NCHUNK 4                 // stream blocks per row
#define CHUNK  (Vv / NCHUNK)     // 8000 floats per chunk

// scratch (allocation-free rule: __device__ globals)
__device__ int   g_leader[Bv * Iv];
__device__ float g_encW[Bv * Iv];
__device__ int   g_nu[Bv];
__device__ float g_pg[Bv * Tv];
__device__ float g_base[Bv * Tv];
__device__ float g_eb[Bv * Tv * Iv];   // e*base per (row, slot-owner i); 4MB

// ---------------------------------------------------------------------------
// Prep: blocks [0,128) encW (one warp per (b,i) row); blocks [128,132) dedup.
// ---------------------------------------------------------------------------
__global__ __launch_bounds__(512) void prep_kernel(const int* __restrict__ tok,
                                                   const float* __restrict__ enc,
                                                   const float* __restrict__ W) {
    __shared__ int st[Iv];
    if (blockIdx.x < 128) {
        int warp = blockIdx.x * 16 + (threadIdx.x >> 5);   // 0..2047 = b*I+i
        int lane = threadIdx.x & 31;
        const float* row = enc + (long)warp * Dv;
        float acc = 0.f;
        #pragma unroll
        for (int d = lane; d < Dv; d += 32) acc = fmaf(row[d], W[d], acc);
        #pragma unroll
        for (int o = 16; o; o >>= 1) acc += __shfl_down_sync(0xffffffffu, acc, o);
        if (lane == 0) g_encW[warp] = acc;
    } else {
        int b = blockIdx.x - 128;
        int i = threadIdx.x;
        st[i] = tok[b * Iv + i];
        __syncthreads();
        int me = st[i];
        int lead = i;
        #pragma unroll 8
        for (int j = 0; j < Iv; j++) {
            bool m = (st[j] == me) && (j < lead);
            lead = m ? j : lead;
        }
        g_leader[b * Iv + i] = lead;
        int n = __syncthreads_count(lead == i);
        if (i == 0) g_nu[b] = n;
    }
}

// ---------------------------------------------------------------------------
// Block reduction (512 threads)
// ---------------------------------------------------------------------------
__device__ __forceinline__ float block_reduce_sum(float v, float* sred) {
    int lane = threadIdx.x & 31;
    int w = threadIdx.x >> 5;
    #pragma unroll
    for (int o = 16; o; o >>= 1) v += __shfl_down_sync(0xffffffffu, v, o);
    if (lane == 0) sred[w] = v;
    __syncthreads();
    if (w == 0) {
        float x = (lane < 16) ? sred[lane] : 0.f;
        #pragma unroll
        for (int o = 8; o; o >>= 1) x += __shfl_down_sync(0xffffffffu, x, o);
        if (lane == 0) sred[0] = x;
    }
    __syncthreads();
    float r = sred[0];
    __syncthreads();
    return r;
}

// ---------------------------------------------------------------------------
// Row kernel: all latency/reduction work per (b,t) row; no bulk streaming.
// Writes g_pg, g_base, g_eb scratch and the p_gen output.
// ---------------------------------------------------------------------------
__global__ __launch_bounds__(512) void row_kernel(
    const int* __restrict__ tok,
    const float* __restrict__ tar,
    const float* __restrict__ dec,
    const float* __restrict__ attn_heads,
    const float* __restrict__ W,
    const float* __restrict__ bpg,
    float* __restrict__ out)
{
    const int row = blockIdx.x;        // b*T + t
    const int b   = row >> 9;
    const int t   = row & 511;
    const int tid = threadIdx.x;

    __shared__ float ss[Iv];
    __shared__ float sred[32];

    const int lead = g_leader[b * Iv + tid];
    ss[tid] = 0.f;

    // head-mean attention weight for column i = tid
    float w = 0.f;
    long base_a = ((long)b * Hv) * ((long)Tv * Iv) + (long)t * Iv + tid;
    #pragma unroll
    for (int h = 0; h < Hv; h++) w += attn_heads[base_a + (long)h * Tv * Iv];
    w *= 0.125f;

    // p_gen partials: collapsed context + dec/tar dots
    float acc = w * g_encW[b * Iv + tid];
    acc = fmaf(dec[(long)row * Dv + tid], W[Dv + tid], acc);
    acc = fmaf(tar[(long)row * Dv + tid], W[2 * Dv + tid], acc);

    __syncthreads();                   // ss zeroed
    atomicAdd(&ss[lead], w);

    float pgsum = block_reduce_sum(acc, sred);  // barriers publish atomics

    const bool active = (lead == tid);
    float e = active ? expf(ss[tid]) : 0.f;
    float esum = block_reduce_sum(e, sred);

    const float denom = esum + (float)(Vv - g_nu[b]);
    const float base  = 1.f / denom;
    const float pg    = 1.f / (1.f + expf(-(pgsum + bpg[0])));

    g_eb[(long)row * Iv + tid] = e * base;     // 0 for inactive slots
    if (tid == 0) {
        g_pg[row]   = pg;
        g_base[row] = base;
        out[2L * Bv * Tv * Vv + row] = pg;     // p_gen (B,T)
    }
}

// ---------------------------------------------------------------------------
// Stream kernel: pure bandwidth. 4 blocks per row, each owns an 8000-float
// vocab chunk. Streams final+pointer, then applies in-chunk fixups.
// ---------------------------------------------------------------------------
__global__ __launch_bounds__(512) void stream_kernel(
    const int* __restrict__ tok,
    const float* __restrict__ gen,
    float* __restrict__ out)
{
    const int row = blockIdx.x >> 2;       // b*T + t
    const int c   = blockIdx.x & (NCHUNK - 1);
    const int b   = row >> 9;
    const int tid = threadIdx.x;

    const float pg   = g_pg[row];
    const float base = g_base[row];
    const float omp  = 1.f - pg;
    const float pb   = omp * base;
    const int   lo   = c * CHUNK;

    // hoisted fixup state: slot owner i = tid, applies iff token lands in chunk
    const int  lead = g_leader[b * Iv + tid];
    const int  v    = tok[b * Iv + tid];
    const bool act  = (lead == tid) && (v >= lo) && (v < lo + CHUNK);
    float gscat = 0.f, eb = 0.f;
    if (act) {
        gscat = __ldg(&gen[(long)row * Vv + v]);
        eb    = g_eb[(long)row * Iv + tid];
    }

    // stream this chunk: 2000 float4
    const float4* g4 = (const float4*)(gen + (long)row * Vv);
    float4* f4 = (float4*)(out + (long)row * Vv);
    float4* p4 = (float4*)(out + (long)(Bv * Tv) * Vv + (long)row * Vv);
    const float4 pconst = make_float4(base, base, base, base);
    const int q0 = lo >> 2, q1 = q0 + (CHUNK >> 2);

    #pragma unroll 4
    for (int q = q0 + tid; q < q1; q += 512) {
        float4 g = __ldcs(&g4[q]);
        float4 f;
        f.x = fmaf(pg, g.x, pb);
        f.y = fmaf(pg, g.y, pb);
        f.z = fmaf(pg, g.z, pb);
        f.w = fmaf(pg, g.w, pb);
        __stcs(&f4[q], f);
        __stcs(&p4[q], pconst);
    }
    __syncthreads();                      // order fixup stores after stream

    if (act) {
        out[(long)(Bv * Tv) * Vv + (long)row * Vv + v] = eb;
        out[(long)row * Vv + v] = fmaf(pg, gscat, omp * eb);
    }
}

// ---------------------------------------------------------------------------
// Launch. Inputs: inp_tokens, tar_embedded, generator_output, enc_output,
// dec_state, attn_heads, W_pgen, b_pgen.
// Output: final (B,T,V) ++ pointer (B,T,V) ++ p_gen (B,T), float32.
// ---------------------------------------------------------------------------
extern "C" void kernel_launch(void* const* d_in, const int* in_sizes, int n_in,
                              void* d_out, int out_size) {
    const int*   tok  = (const int*)  d_in[0];
    const float* tar  = (const float*)d_in[1];
    const float* gen  = (const float*)d_in[2];
    const float* enc  = (const float*)d_in[3];
    const float* dec  = (const float*)d_in[4];
    const float* ah   = (const float*)d_in[5];
    const float* W    = (const float*)d_in[6];
    const float* bpg  = (const float*)d_in[7];
    float* out = (float*)d_out;

    prep_kernel<<<132, 512>>>(tok, enc, W);
    row_kernel<<<Bv * Tv, 512>>>(tok, tar, dec, ah, W, bpg, out);
    stream_kernel<<<Bv * Tv * NCHUNK, 512>>>(tok, gen, out);
}

// round 4
// speedup vs baseline: 1.1003x; 1.0219x over previous
#include <cuda_runtime.h>
#include <cuda_bf16.h>

#define Bv 4
#define Tv 512
#define Iv 512
#define Hv 8
#define Dv 512
#define Vv 32000
#define NCHUNK 4                 // stream blocks per row
#define CHUNK  (Vv / NCHUNK)     // 8000 floats per chunk
#define HSZ 1024                 // dedup hash table slots

// scratch (allocation-free rule: __device__ globals)
__device__ int   g_leader[Bv * Iv];
__device__ float g_encW[Bv * Iv];
__device__ int   g_nu[Bv];
__device__ float g_pg[Bv * Tv];
__device__ float g_base[Bv * Tv];
__device__ float g_eb[Bv * Tv * Iv];   // e*base per (row, slot-owner i); 4MB

// ---------------------------------------------------------------------------
// Prep: blocks [0,128) encW (one warp per (b,i) row, float4); blocks
// [128,132) per-batch dedup via smem hash (O(I) instead of O(I^2)).
// ---------------------------------------------------------------------------
__global__ __launch_bounds__(512) void prep_kernel(const int* __restrict__ tok,
                                                   const float* __restrict__ enc,
                                                   const float* __restrict__ W) {
    if (blockIdx.x < 128) {
        int warp = blockIdx.x * 16 + (threadIdx.x >> 5);   // 0..2047 = b*I+i
        int lane = threadIdx.x & 31;
        const float4* row = (const float4*)(enc + (long)warp * Dv);
        const float4* W4  = (const float4*)W;
        float acc = 0.f;
        #pragma unroll
        for (int k = 0; k < 4; k++) {
            int q = lane + 32 * k;              // 128 float4 per row
            float4 r = __ldg(&row[q]);
            float4 w = __ldg(&W4[q]);
            acc = fmaf(r.x, w.x, acc);
            acc = fmaf(r.y, w.y, acc);
            acc = fmaf(r.z, w.z, acc);
            acc = fmaf(r.w, w.w, acc);
        }
        #pragma unroll
        for (int o = 16; o; o >>= 1) acc += __shfl_down_sync(0xffffffffu, acc, o);
        if (lane == 0) g_encW[warp] = acc;
    } else {
        __shared__ int hkey[HSZ];
        __shared__ int hval[HSZ];
        int b = blockIdx.x - 128;
        int i = threadIdx.x;
        #pragma unroll
        for (int s = i; s < HSZ; s += Iv) { hkey[s] = -1; hval[s] = 0x7fffffff; }
        int me = tok[b * Iv + i];
        __syncthreads();
        // insert: find/claim slot for token `me`, record min index
        unsigned h = ((unsigned)me * 2654435761u) & (HSZ - 1);
        int slot;
        while (true) {
            int k = atomicCAS(&hkey[h], -1, me);
            if (k == -1 || k == me) { slot = (int)h; break; }
            h = (h + 1) & (HSZ - 1);
        }
        atomicMin(&hval[slot], i);
        __syncthreads();
        int lead = hval[slot];
        g_leader[b * Iv + i] = lead;
        int n = __syncthreads_count(lead == i);
        if (i == 0) g_nu[b] = n;
    }
}

// ---------------------------------------------------------------------------
// Dual block reduction: sums v1 and v2 across 512 threads with one barrier set.
// ---------------------------------------------------------------------------
__device__ __forceinline__ void block_reduce_sum2(float v1, float v2,
                                                  float* s1, float* s2,
                                                  float& r1, float& r2) {
    int lane = threadIdx.x & 31;
    int w = threadIdx.x >> 5;
    #pragma unroll
    for (int o = 16; o; o >>= 1) {
        v1 += __shfl_down_sync(0xffffffffu, v1, o);
        v2 += __shfl_down_sync(0xffffffffu, v2, o);
    }
    if (lane == 0) { s1[w] = v1; s2[w] = v2; }
    __syncthreads();
    if (w == 0) {
        float x1 = (lane < 16) ? s1[lane] : 0.f;
        float x2 = (lane < 16) ? s2[lane] : 0.f;
        #pragma unroll
        for (int o = 8; o; o >>= 1) {
            x1 += __shfl_down_sync(0xffffffffu, x1, o);
            x2 += __shfl_down_sync(0xffffffffu, x2, o);
        }
        if (lane == 0) { s1[0] = x1; s2[0] = x2; }
    }
    __syncthreads();
    r1 = s1[0];
    r2 = s2[0];
}

// ---------------------------------------------------------------------------
// Row kernel: all latency/reduction work per (b,t) row; no bulk streaming.
// ---------------------------------------------------------------------------
__global__ __launch_bounds__(512) void row_kernel(
    const int* __restrict__ tok,
    const float* __restrict__ tar,
    const float* __restrict__ dec,
    const float* __restrict__ attn_heads,
    const float* __restrict__ W,
    const float* __restrict__ bpg,
    float* __restrict__ out)
{
    const int row = blockIdx.x;        // b*T + t
    const int b   = row >> 9;
    const int t   = row & 511;
    const int tid = threadIdx.x;

    __shared__ float ss[Iv];
    __shared__ float s1[32], s2[32];

    const int lead = g_leader[b * Iv + tid];
    ss[tid] = 0.f;

    // head-mean attention weight for column i = tid
    float w = 0.f;
    long base_a = ((long)b * Hv) * ((long)Tv * Iv) + (long)t * Iv + tid;
    #pragma unroll
    for (int h = 0; h < Hv; h++) w += attn_heads[base_a + (long)h * Tv * Iv];
    w *= 0.125f;

    __syncthreads();                   // ss zeroed
    atomicAdd(&ss[lead], w);

    // p_gen partials overlap the atomics
    float acc = w * g_encW[b * Iv + tid];
    acc = fmaf(dec[(long)row * Dv + tid], W[Dv + tid], acc);
    acc = fmaf(tar[(long)row * Dv + tid], W[2 * Dv + tid], acc);

    __syncthreads();                   // publish atomics

    const bool active = (lead == tid);
    float e = active ? expf(ss[tid]) : 0.f;

    float pgsum, esum;
    block_reduce_sum2(acc, e, s1, s2, pgsum, esum);

    const float denom = esum + (float)(Vv - g_nu[b]);
    const float base  = 1.f / denom;
    const float pg    = 1.f / (1.f + expf(-(pgsum + bpg[0])));

    g_eb[(long)row * Iv + tid] = e * base;     // 0 for inactive slots
    if (tid == 0) {
        g_pg[row]   = pg;
        g_base[row] = base;
        out[2L * Bv * Tv * Vv + row] = pg;     // p_gen (B,T)
    }
}

// ---------------------------------------------------------------------------
// Stream kernel: pure bandwidth. 4 blocks per row, each owns an 8000-float
// vocab chunk. Streams final+pointer, then applies in-chunk fixups.
// ---------------------------------------------------------------------------
__global__ __launch_bounds__(512) void stream_kernel(
    const int* __restrict__ tok,
    const float* __restrict__ gen,
    float* __restrict__ out)
{
    const int row = blockIdx.x >> 2;       // b*T + t
    const int c   = blockIdx.x & (NCHUNK - 1);
    const int b   = row >> 9;
    const int tid = threadIdx.x;

    const float pg   = g_pg[row];
    const float base = g_base[row];
    const float omp  = 1.f - pg;
    const float pb   = omp * base;
    const int   lo   = c * CHUNK;

    // hoisted fixup state: slot owner i = tid, applies iff token lands in chunk
    const int  lead = g_leader[b * Iv + tid];
    const int  v    = tok[b * Iv + tid];
    const bool act  = (lead == tid) && (v >= lo) && (v < lo + CHUNK);
    float gscat = 0.f, eb = 0.f;
    if (act) {
        gscat = __ldg(&gen[(long)row * Vv + v]);
        eb    = g_eb[(long)row * Iv + tid];
    }

    // stream this chunk: 2000 float4
    const float4* g4 = (const float4*)(gen + (long)row * Vv);
    float4* f4 = (float4*)(out + (long)row * Vv);
    float4* p4 = (float4*)(out + (long)(Bv * Tv) * Vv + (long)row * Vv);
    const float4 pconst = make_float4(base, base, base, base);
    const int q0 = lo >> 2, q1 = q0 + (CHUNK >> 2);

    #pragma unroll 4
    for (int q = q0 + tid; q < q1; q += 512) {
        float4 g = __ldcs(&g4[q]);
        float4 f;
        f.x = fmaf(pg, g.x, pb);
        f.y = fmaf(pg, g.y, pb);
        f.z = fmaf(pg, g.z, pb);
        f.w = fmaf(pg, g.w, pb);
        __stcs(&f4[q], f);
        __stcs(&p4[q], pconst);
    }
    __syncthreads();                      // order fixup stores after stream

    if (act) {
        out[(long)(Bv * Tv) * Vv + (long)row * Vv + v] = eb;
        out[(long)row * Vv + v] = fmaf(pg, gscat, omp * eb);
    }
}

// ---------------------------------------------------------------------------
// Launch. Inputs: inp_tokens, tar_embedded, generator_output, enc_output,
// dec_state, attn_heads, W_pgen, b_pgen.
// Output: final (B,T,V) ++ pointer (B,T,V) ++ p_gen (B,T), float32.
// ---------------------------------------------------------------------------
extern "C" void kernel_launch(void* const* d_in, const int* in_sizes, int n_in,
                              void* d_out, int out_size) {
    const int*   tok  = (const int*)  d_in[0];
    const float* tar  = (const float*)d_in[1];
    const float* gen  = (const float*)d_in[2];
    const float* enc  = (const float*)d_in[3];
    const float* dec  = (const float*)d_in[4];
    const float* ah   = (const float*)d_in[5];
    const float* W    = (const float*)d_in[6];
    const float* bpg  = (const float*)d_in[7];
    float* out = (float*)d_out;

    prep_kernel<<<132, 512>>>(tok, enc, W);
    row_kernel<<<Bv * Tv, 512>>>(tok, tar, dec, ah, W, bpg, out);
    stream_kernel<<<Bv * Tv * NCHUNK, 512>>>(tok, gen, out);
}